// round 14
// baseline (speedup 1.0000x reference)
#include <cuda_runtime.h>
#include <math_constants.h>
#include <cstdint>

#define NQ   16384
#define NPIX 3600
#define ND   131072
#define DDIM 500
#define DP   512   // padded K
#define TOPK 8
#define CAP  16

#define QS    (127.0f / 6.0f)                        // quant scale
#define QDEQ2 ((6.0f / 127.0f) * (6.0f / 127.0f))    // dequant^2 for dot

// ---------------- scratch (__device__ globals; no allocation) ----------------
__device__ float g_query[(size_t)NQ * DP];   // emulated ref query (f32), padded
__device__ char  g_qi8[(size_t)NQ * DP];     // int8 query (pass-1)
__device__ char  g_di8[(size_t)ND * DP];     // int8 dict  (pass-1), padded
__device__ float g_xn_emu[ND];               // emulated fp32 ||d||^2 (refine)
__device__ float g_xnh[ND];                  // 0.5*||d||^2 (pass-1)
__device__ float g_mean32[NQ];
__device__ int   g_cand[(size_t)NQ * CAP];

__device__ __forceinline__ uint32_t s2u(const void* p) {
    uint32_t a;
    asm("{ .reg .u64 t; cvta.to.shared.u64 t, %1; cvt.u32.u64 %0, t; }"
        : "=r"(a) : "l"(p));
    return a;
}

#define LDMATRIX_X4(r, addr)                                                   \
    asm volatile("ldmatrix.sync.aligned.m8n8.x4.shared.b16 {%0,%1,%2,%3}, [%4];" \
        : "=r"((r)[0]), "=r"((r)[1]), "=r"((r)[2]), "=r"((r)[3]) : "r"(addr))
#define MMAI8(d, a, b)                                                         \
    asm volatile("mma.sync.aligned.m16n8k32.row.col.s32.s8.s8.s32 "            \
        "{%0,%1,%2,%3}, {%4,%5,%6,%7}, {%8,%9}, {%0,%1,%2,%3};"                \
        : "+r"((d)[0]), "+r"((d)[1]), "+r"((d)[2]), "+r"((d)[3])               \
        : "r"((a)[0]), "r"((a)[1]), "r"((a)[2]), "r"((a)[3]),                  \
          "r"((b)[0]), "r"((b)[1]))

__device__ __forceinline__ char quant1(float v) {
    int t = __float2int_rn(v * QS);
    t = max(-127, min(127, t));
    return (char)t;
}

// ---------------- K0: row means (fp64) ----------------
__global__ void rowmean_kernel(const float* __restrict__ E) {
    int row = blockIdx.x;
    const float* r = E + (size_t)row * NPIX;
    double s = 0.0;
    for (int i = threadIdx.x; i < NPIX; i += 256) s += (double)r[i];
    __shared__ double sh[8];
    #pragma unroll
    for (int o = 16; o; o >>= 1) s += __shfl_down_sync(0xffffffffu, s, o);
    if ((threadIdx.x & 31) == 0) sh[threadIdx.x >> 5] = s;
    __syncthreads();
    if (threadIdx.x == 0) {
        double t = 0.0;
        #pragma unroll
        for (int w = 0; w < 8; w++) t += sh[w];
        g_mean32[row] = __fdiv_rn((float)t, (float)NPIX);
    }
}

// ---------------- K1: emulated dict norms (XLA-style warp-strided fp32) ----------------
__global__ void dictnorm_kernel(const float* __restrict__ Dm) {
    int row = blockIdx.x * 4 + (threadIdx.x >> 5);
    int lane = threadIdx.x & 31;
    const float* src = Dm + (size_t)row * DDIM;
    float s = 0.f;
    #pragma unroll
    for (int u = 0; u < 16; u++) {
        int j = lane + u * 32;
        if (j < DDIM) {
            float v = src[j];
            s = __fadd_rn(s, __fmul_rn(v, v));
        }
    }
    #pragma unroll
    for (int o = 16; o; o >>= 1)
        s = __fadd_rn(s, __shfl_down_sync(0xffffffffu, s, o));
    if (lane == 0) {
        g_xn_emu[row] = s;
        g_xnh[row] = 0.5f * s;
    }
}

// ---------------- K2: dict -> int8 (padded to DP) ----------------
__global__ void d8_kernel(const float* __restrict__ Dm) {
    size_t idx = (size_t)blockIdx.x * 256 + threadIdx.x;   // ND*128 units of 4
    int row = (int)(idx >> 7);
    int t = (int)(idx & 127);
    char4 o = make_char4(0, 0, 0, 0);
    if (t < 125) {   // 125*4 = 500
        float4 v = *(const float4*)(Dm + (size_t)row * DDIM + t * 4);
        o = make_char4(quant1(v.x), quant1(v.y), quant1(v.z), quant1(v.w));
    }
    *(char4*)(g_di8 + (size_t)row * DP + t * 4) = o;
}

// ---- K3: emulated query GEMM, 32 q/block, chunked staging (exact k order) ----
#define KCH 600   // 3600 = 6 * 600
__global__ void __launch_bounds__(512) queryemu_kernel(const float* __restrict__ E,
                                                       const float* __restrict__ P) {
    extern __shared__ float cs[];   // [KCH][36] : 32 centered values + pad 4
    __shared__ float ms[32];
    int qb = blockIdx.x * 32;
    int t = threadIdx.x;
    if (t < 32) ms[t] = g_mean32[qb + t];
    __syncthreads();

    float a[32];
    #pragma unroll
    for (int q = 0; q < 32; q++) a[q] = 0.f;

    for (int k0 = 0; k0 < NPIX; k0 += KCH) {
        __syncthreads();   // previous chunk fully consumed
        for (int q = 0; q < 32; q++) {
            float m = ms[q];
            const float* erow = E + (size_t)(qb + q) * NPIX + k0;
            for (int k = t; k < KCH; k += 512)
                cs[k * 36 + q] = __fsub_rn(erow[k], m);
        }
        __syncthreads();
        if (t < DDIM) {
            const float* p = P + (size_t)k0 * DDIM + t;
            for (int k = 0; k < KCH; k++) {
                float pv = p[(size_t)k * DDIM];
                const float4* c4 = (const float4*)(cs + k * 36);
                #pragma unroll
                for (int j = 0; j < 8; j++) {
                    float4 cv = c4[j];
                    a[j * 4 + 0] = __fmaf_rn(cv.x, pv, a[j * 4 + 0]);
                    a[j * 4 + 1] = __fmaf_rn(cv.y, pv, a[j * 4 + 1]);
                    a[j * 4 + 2] = __fmaf_rn(cv.z, pv, a[j * 4 + 2]);
                    a[j * 4 + 3] = __fmaf_rn(cv.w, pv, a[j * 4 + 3]);
                }
            }
        }
    }
    if (t < DDIM) {
        #pragma unroll
        for (int q = 0; q < 32; q++)
            g_query[(size_t)(qb + q) * DP + t] = a[q];
    } else {
        #pragma unroll
        for (int q = 0; q < 32; q++)
            g_query[(size_t)(qb + q) * DP + t] = 0.f;
    }
}

// ---------------- K4: query f32 -> int8 ----------------
__global__ void q8_kernel() {
    size_t idx = (size_t)blockIdx.x * 256 + threadIdx.x;   // NQ*DP/4 units
    float4 v = ((const float4*)g_query)[idx];
    ((char4*)g_qi8)[idx] =
        make_char4(quant1(v.x), quant1(v.y), quant1(v.z), quant1(v.w));
}

// ------------- K5: INT8 MMA pass-1: scores + top-16 capture -------------
// 128 CTAs x 256 thr (8 warps: wm in [0,2), wn in [0,4)).
// A: [128 q][512 k] int8 smem (32 16B-chunks/row, XOR swizzle c^(r&7)).
// B: double-buffered [128 n][256 k] int8 chunks, stored [n][k] (col-major KxN)
//    => non-trans ldmatrix yields s8 B fragments. acc: 64x32 s32 per warp.
#define SA    0
#define SB    65536                  // 2 x 32768
#define SS    131072                 // scores 128 x 65 f32 = 33280
#define SX    (SS + 128 * 65 * 4)
#define SMEM_KNN (SX + 512)

__global__ void __launch_bounds__(256) knn_i8() {
    extern __shared__ char sm[];
    float* Ssc  = (float*)(sm + SS);
    float* sxnh = (float*)(sm + SX);
    uint32_t sbase = s2u(sm);
    int tid = threadIdx.x;
    int w = tid >> 5, l = tid & 31;
    int wm = w >> 2, wn = w & 3;
    int qb = blockIdx.x * 128;

    // Load A (queries int8) with swizzle: 4096 16B-chunks
    {
        const uint4* src = (const uint4*)(g_qi8 + (size_t)qb * DP);
        #pragma unroll 4
        for (int i = 0; i < 16; i++) {
            int idx = i * 256 + tid;
            int r = idx >> 5, c = idx & 31;
            uint4 v = src[r * 32 + c];
            *(uint4*)(sm + SA + (((r << 5) + (c ^ (r & 7))) << 4)) = v;
        }
    }

    float ts[CAP];
    int   ti[CAP];
    #pragma unroll
    for (int r = 0; r < CAP; r++) { ts[r] = -CUDART_INF_F; ti[r] = 0; }

    int srow = tid & 127, shalf = tid >> 7;

    for (int t = 0; t < ND / 128; t++) {
        int nb = t * 128;
        if (tid < 128) sxnh[tid] = g_xnh[nb + tid];

        const uint4* dsrc = (const uint4*)(g_di8 + (size_t)nb * DP);
        uint4 pre[8];
        // kc0 chunk -> buf 0  (row n: 32 chunks/row; kc0 = chunks 0..15)
        #pragma unroll
        for (int i = 0; i < 8; i++) {
            int idx = i * 256 + tid;
            int n = idx >> 4, c = idx & 15;
            pre[i] = dsrc[n * 32 + c];
        }
        #pragma unroll
        for (int i = 0; i < 8; i++) {
            int idx = i * 256 + tid;
            int n = idx >> 4, c = idx & 15;
            *(uint4*)(sm + SB + (((n << 4) + (c ^ (n & 7))) << 4)) = pre[i];
        }
        __syncthreads();

        int acc[4][4][4];
        #pragma unroll
        for (int mt = 0; mt < 4; mt++)
            #pragma unroll
            for (int nt = 0; nt < 4; nt++)
                #pragma unroll
                for (int rr = 0; rr < 4; rr++) acc[mt][nt][rr] = 0;

        #pragma unroll
        for (int kc = 0; kc < 2; kc++) {
            if (kc == 0) {   // prefetch kc1 (chunks 16..31)
                #pragma unroll
                for (int i = 0; i < 8; i++) {
                    int idx = i * 256 + tid;
                    int n = idx >> 4, c = idx & 15;
                    pre[i] = dsrc[n * 32 + 16 + c];
                }
            }
            uint32_t Bcur = sbase + SB + (kc & 1) * 32768;
            #pragma unroll
            for (int ks = 0; ks < 8; ks++) {   // k32 per mma step
                uint32_t a[4][4], b[4][2];
                #pragma unroll
                for (int mt = 0; mt < 4; mt++) {
                    int r = wm * 64 + mt * 16 + (l & 15);
                    int c = kc * 16 + ks * 2 + (l >> 4);
                    uint32_t ad = sbase + SA + (((r << 5) + (c ^ (r & 7))) << 4);
                    LDMATRIX_X4(a[mt], ad);
                }
                #pragma unroll
                for (int p2 = 0; p2 < 2; p2++) {
                    int n = wn * 32 + p2 * 16 + ((l >> 4) & 1) * 8 + (l & 7);
                    int c = ks * 2 + ((l >> 3) & 1);
                    uint32_t ad = Bcur + (((n << 4) + (c ^ (n & 7))) << 4);
                    uint32_t r4[4];
                    LDMATRIX_X4(r4, ad);
                    // r0=(n0-7,k0-15)->b0, r1=(n0-7,k16-31)->b1; r2/r3 n8-15
                    b[p2 * 2 + 0][0] = r4[0]; b[p2 * 2 + 0][1] = r4[1];
                    b[p2 * 2 + 1][0] = r4[2]; b[p2 * 2 + 1][1] = r4[3];
                }
                #pragma unroll
                for (int mt = 0; mt < 4; mt++)
                    #pragma unroll
                    for (int nt = 0; nt < 4; nt++)
                        MMAI8(acc[mt][nt], a[mt], b[nt]);
            }
            __syncthreads();
            if (kc == 0) {
                #pragma unroll
                for (int i = 0; i < 8; i++) {
                    int idx = i * 256 + tid;
                    int n = idx >> 4, c = idx & 15;
                    *(uint4*)(sm + SB + 32768 +
                              (((n << 4) + (c ^ (n & 7))) << 4)) = pre[i];
                }
                __syncthreads();
            }
        }

        // Epilogue: dequant + two n-half passes through 128x65 pane
        #pragma unroll
        for (int p = 0; p < 2; p++) {
            if ((wn >> 1) == p) {
                int nloc = (wn & 1) * 32;
                #pragma unroll
                for (int mt = 0; mt < 4; mt++)
                    #pragma unroll
                    for (int nt = 0; nt < 4; nt++) {
                        int r = wm * 64 + mt * 16 + (l >> 2);
                        int cb = nloc + nt * 8 + (l & 3) * 2;
                        int gc = p * 64 + cb;
                        Ssc[r * 65 + cb] =
                            (float)acc[mt][nt][0] * QDEQ2 - sxnh[gc];
                        Ssc[r * 65 + cb + 1] =
                            (float)acc[mt][nt][1] * QDEQ2 - sxnh[gc + 1];
                        Ssc[(r + 8) * 65 + cb] =
                            (float)acc[mt][nt][2] * QDEQ2 - sxnh[gc];
                        Ssc[(r + 8) * 65 + cb + 1] =
                            (float)acc[mt][nt][3] * QDEQ2 - sxnh[gc + 1];
                    }
            }
            __syncthreads();
            int cb = shalf * 32;
            #pragma unroll 8
            for (int cc = 0; cc < 32; cc++) {
                float s = Ssc[srow * 65 + cb + cc];
                if (s > ts[CAP - 1]) {
                    ts[CAP - 1] = s; ti[CAP - 1] = nb + p * 64 + cb + cc;
                    #pragma unroll
                    for (int r = CAP - 1; r > 0; r--) {
                        if (ts[r] > ts[r - 1]) {
                            float tv = ts[r]; ts[r] = ts[r - 1]; ts[r - 1] = tv;
                            int   tt = ti[r]; ti[r] = ti[r - 1]; ti[r - 1] = tt;
                        }
                    }
                }
            }
            __syncthreads();
        }
    }

    // Final merge: two sorted-desc half-lists per row -> top-16 -> g_cand
    float* msc = Ssc;
    int*   mix = (int*)(sm + SB);
    #pragma unroll
    for (int r = 0; r < CAP; r++) { msc[tid * CAP + r] = ts[r]; mix[tid * CAP + r] = ti[r]; }
    __syncthreads();
    if (tid < 128) {
        int i0 = 0, i1 = 0;
        #pragma unroll
        for (int r = 0; r < CAP; r++) {
            float s0 = msc[tid * CAP + i0];
            float s1 = msc[(tid + 128) * CAP + i1];
            bool take0 = (s0 >= s1);
            int idx = take0 ? mix[tid * CAP + i0] : mix[(tid + 128) * CAP + i1];
            g_cand[(size_t)(qb + tid) * CAP + r] = idx;
            if (take0) i0++; else i1++;
        }
    }
}

// -------- K6: refine — reference-arithmetic emulation over 16 candidates ----
__global__ void __launch_bounds__(128) refine_kernel(const float* __restrict__ Dm,
                                                     float* __restrict__ out) {
    __shared__ float qs[4][DP];
    int qb = blockIdx.x * 4;
    int w = threadIdx.x >> 5;
    int lane = threadIdx.x & 31;
    int q = qb + w;

    for (int i = threadIdx.x; i < 4 * DP / 4; i += 128) {
        int qr = i / (DP / 4), c4 = i % (DP / 4);
        *(float4*)&qs[qr][c4 * 4] =
            *(const float4*)(g_query + (size_t)(qb + qr) * DP + c4 * 4);
    }
    __syncthreads();

    float s = 0.f;
    #pragma unroll
    for (int u = 0; u < 16; u++) {
        int j = lane + u * 32;
        if (j < DDIM) {
            float v = qs[w][j];
            s = __fadd_rn(s, __fmul_rn(v, v));
        }
    }
    #pragma unroll
    for (int o = 16; o; o >>= 1)
        s = __fadd_rn(s, __shfl_down_sync(0xffffffffu, s, o));
    float qn = __shfl_sync(0xffffffffu, s, 0);

    float dzc = CUDART_INF_F;
    int   idxc = 0;
    if (lane < CAP) {
        idxc = g_cand[(size_t)q * CAP + lane];
        const float* drow = Dm + (size_t)idxc * DDIM;
        float dot = 0.f;
        for (int k = 0; k < DDIM; k++)
            dot = __fmaf_rn(qs[w][k], drow[k], dot);
        float xn = g_xn_emu[idxc];
        float t1 = __fadd_rn(qn, xn);
        dzc = __fsub_rn(t1, __fmul_rn(2.0f, dot));
    }

    float dz[CAP];
    int   ci[CAP];
    #pragma unroll
    for (int c = 0; c < CAP; c++) {
        dz[c] = __shfl_sync(0xffffffffu, dzc, c);
        ci[c] = __shfl_sync(0xffffffffu, idxc, c);
    }
    if (lane == 0) {
        #pragma unroll
        for (int r = 0; r < TOPK; r++) {
            int best = r;
            #pragma unroll
            for (int c = 0; c < CAP; c++) {
                if (c <= r) continue;
                if (dz[c] < dz[best] || (dz[c] == dz[best] && ci[c] < ci[best]))
                    best = c;
            }
            float td = dz[r]; dz[r] = dz[best]; dz[best] = td;
            int   tc = ci[r]; ci[r] = ci[best]; ci[best] = tc;
            out[(size_t)q * TOPK + r] = (float)ci[r];
        }
    }
}

extern "C" void kernel_launch(void* const* d_in, const int* in_sizes, int n_in,
                              void* d_out, int out_size) {
    const float* E  = nullptr;
    const float* P  = nullptr;
    const float* Dm = nullptr;
    for (int i = 0; i < n_in; i++) {
        long long sz = (long long)in_sizes[i];
        if (sz == (long long)NQ * NPIX)        E  = (const float*)d_in[i];
        else if (sz == (long long)NPIX * DDIM) P  = (const float*)d_in[i];
        else if (sz == (long long)ND * DDIM)   Dm = (const float*)d_in[i];
    }
    if (!E || !P || !Dm) {
        int idx[16];
        int m = n_in < 16 ? n_in : 16;
        for (int i = 0; i < m; i++) idx[i] = i;
        for (int a = 0; a < m; a++)
            for (int b = a + 1; b < m; b++)
                if ((long long)in_sizes[idx[b]] > (long long)in_sizes[idx[a]]) {
                    int tmp = idx[a]; idx[a] = idx[b]; idx[b] = tmp;
                }
        if (m >= 3) { Dm = (const float*)d_in[idx[0]];
                      E  = (const float*)d_in[idx[1]];
                      P  = (const float*)d_in[idx[2]]; }
    }
    if (!E || !P || !Dm) return;

    float* out = (float*)d_out;

    static bool attr_set = false;
    if (!attr_set) {
        cudaFuncSetAttribute(queryemu_kernel,
                             cudaFuncAttributeMaxDynamicSharedMemorySize,
                             KCH * 36 * (int)sizeof(float));
        cudaFuncSetAttribute(knn_i8,
                             cudaFuncAttributeMaxDynamicSharedMemorySize,
                             SMEM_KNN);
        attr_set = true;
    }

    rowmean_kernel<<<NQ, 256>>>(E);
    dictnorm_kernel<<<ND / 4, 128>>>(Dm);
    d8_kernel<<<(int)(((size_t)ND * 128) / 256), 256>>>(Dm);
    queryemu_kernel<<<NQ / 32, 512, KCH * 36 * sizeof(float)>>>(E, P);
    q8_kernel<<<(int)(((size_t)NQ * DP / 4) / 256), 256>>>();
    knn_i8<<<NQ / 128, 256, SMEM_KNN>>>();
    refine_kernel<<<NQ / 4, 128>>>(Dm, out);
}

// round 15
// speedup vs baseline: 1.5752x; 1.5752x over previous
#include <cuda_runtime.h>
#include <cuda_bf16.h>
#include <math_constants.h>
#include <cstdint>

#define NQ   16384
#define NPIX 3600
#define ND   131072
#define DDIM 500
#define DP   512   // padded K
#define TOPK 8
#define CAP  16
#define SPLIT 16                    // dict splits per q-tile
#define UNITS (128 * SPLIT)         // 2048 work units
#define NWORK 148                   // persistent workers

// ---------------- scratch (__device__ globals; no allocation) ----------------
__device__ float          g_query[(size_t)NQ * DP];   // emulated ref query (f32)
__device__ __nv_bfloat16  g_qbf[(size_t)NQ * DP];     // bf16 query (pass-1)
__device__ __nv_bfloat16  g_dbf[(size_t)ND * DP];     // bf16 dict  (pass-1)
__device__ float          g_xn_emu[ND];               // emulated fp32 ||d||^2
__device__ float          g_xnh[ND];                  // 0.5*||d||^2 (pass-1)
__device__ float          g_mean32[NQ];
__device__ float          g_part_s[(size_t)NQ * SPLIT * CAP];
__device__ int            g_part_i[(size_t)NQ * SPLIT * CAP];
__device__ int            g_cand[(size_t)NQ * CAP];

__device__ __forceinline__ uint32_t s2u(const void* p) {
    uint32_t a;
    asm("{ .reg .u64 t; cvta.to.shared.u64 t, %1; cvt.u32.u64 %0, t; }"
        : "=r"(a) : "l"(p));
    return a;
}

#define LDMATRIX_X4(r, addr)                                                   \
    asm volatile("ldmatrix.sync.aligned.m8n8.x4.shared.b16 {%0,%1,%2,%3}, [%4];" \
        : "=r"((r)[0]), "=r"((r)[1]), "=r"((r)[2]), "=r"((r)[3]) : "r"(addr))
#define MMA16816(d, a, b)                                                      \
    asm volatile("mma.sync.aligned.m16n8k16.row.col.f32.bf16.bf16.f32 "        \
        "{%0,%1,%2,%3}, {%4,%5,%6,%7}, {%8,%9}, {%0,%1,%2,%3};"                \
        : "+f"((d)[0]), "+f"((d)[1]), "+f"((d)[2]), "+f"((d)[3])               \
        : "r"((a)[0]), "r"((a)[1]), "r"((a)[2]), "r"((a)[3]),                  \
          "r"((b)[0]), "r"((b)[1]))
#define CP_ASYNC16(dst, src)                                                   \
    asm volatile("cp.async.cg.shared.global [%0], [%1], 16;"                   \
        :: "r"(dst), "l"(__cvta_generic_to_global(src)) : "memory")
#define CP_COMMIT() asm volatile("cp.async.commit_group;" ::: "memory")
#define CP_WAIT1()  asm volatile("cp.async.wait_group 1;" ::: "memory")

// ---------------- K0: row means (fp64) ----------------
__global__ void rowmean_kernel(const float* __restrict__ E) {
    int row = blockIdx.x;
    const float* r = E + (size_t)row * NPIX;
    double s = 0.0;
    for (int i = threadIdx.x; i < NPIX; i += 256) s += (double)r[i];
    __shared__ double sh[8];
    #pragma unroll
    for (int o = 16; o; o >>= 1) s += __shfl_down_sync(0xffffffffu, s, o);
    if ((threadIdx.x & 31) == 0) sh[threadIdx.x >> 5] = s;
    __syncthreads();
    if (threadIdx.x == 0) {
        double t = 0.0;
        #pragma unroll
        for (int w = 0; w < 8; w++) t += sh[w];
        g_mean32[row] = __fdiv_rn((float)t, (float)NPIX);
    }
}

// ---------------- K1: dict prep: bf16 + emulated fp32 norms ----------------
__global__ void dictprep_kernel(const float* __restrict__ Dm) {
    int row = blockIdx.x * 4 + (threadIdx.x >> 5);
    int lane = threadIdx.x & 31;
    const float* src = Dm + (size_t)row * DDIM;
    __nv_bfloat16* dbf = g_dbf + (size_t)row * DP;
    float s = 0.f;
    #pragma unroll
    for (int u = 0; u < 16; u++) {
        int j = lane + u * 32;
        float v = (j < DDIM) ? src[j] : 0.f;
        dbf[j] = __float2bfloat16(v);
        if (j < DDIM) s = __fadd_rn(s, __fmul_rn(v, v));
    }
    #pragma unroll
    for (int o = 16; o; o >>= 1)
        s = __fadd_rn(s, __shfl_down_sync(0xffffffffu, s, o));
    if (lane == 0) {
        g_xn_emu[row] = s;
        g_xnh[row] = 0.5f * s;
    }
}

// ---- K2: emulated query GEMM, 32 q/block, chunked staging (exact k order) ----
#define KCH 600
__global__ void __launch_bounds__(512) queryemu_kernel(const float* __restrict__ E,
                                                       const float* __restrict__ P) {
    extern __shared__ float cs[];   // [KCH][36]
    __shared__ float ms[32];
    int qb = blockIdx.x * 32;
    int t = threadIdx.x;
    if (t < 32) ms[t] = g_mean32[qb + t];
    __syncthreads();

    float a[32];
    #pragma unroll
    for (int q = 0; q < 32; q++) a[q] = 0.f;

    for (int k0 = 0; k0 < NPIX; k0 += KCH) {
        __syncthreads();
        for (int q = 0; q < 32; q++) {
            float m = ms[q];
            const float* erow = E + (size_t)(qb + q) * NPIX + k0;
            for (int k = t; k < KCH; k += 512)
                cs[k * 36 + q] = __fsub_rn(erow[k], m);
        }
        __syncthreads();
        if (t < DDIM) {
            const float* p = P + (size_t)k0 * DDIM + t;
            for (int k = 0; k < KCH; k++) {
                float pv = p[(size_t)k * DDIM];
                const float4* c4 = (const float4*)(cs + k * 36);
                #pragma unroll
                for (int j = 0; j < 8; j++) {
                    float4 cv = c4[j];
                    a[j * 4 + 0] = __fmaf_rn(cv.x, pv, a[j * 4 + 0]);
                    a[j * 4 + 1] = __fmaf_rn(cv.y, pv, a[j * 4 + 1]);
                    a[j * 4 + 2] = __fmaf_rn(cv.z, pv, a[j * 4 + 2]);
                    a[j * 4 + 3] = __fmaf_rn(cv.w, pv, a[j * 4 + 3]);
                }
            }
        }
    }
    if (t < DDIM) {
        #pragma unroll
        for (int q = 0; q < 32; q++)
            g_query[(size_t)(qb + q) * DP + t] = a[q];
    } else {
        #pragma unroll
        for (int q = 0; q < 32; q++)
            g_query[(size_t)(qb + q) * DP + t] = 0.f;
    }
}

// ---------------- K3: query f32 -> bf16 ----------------
__global__ void qbf_kernel() {
    size_t i = (size_t)blockIdx.x * blockDim.x + threadIdx.x;
    if (i < (size_t)NQ * DP) g_qbf[i] = __float2bfloat16(g_query[i]);
}

// ------------- K4: persistent bf16 HMMA pass-1, cp.async pipelined -------------
// 148 CTAs x 256 thr; 2048 units (qtile x 16 dict-splits of 64 tiles).
// A: [128 q][512 k] bf16 smem swizzled. B: 2 x 32KB cp.async double buffer.
#define SA    0
#define SB    131072                 // 2 x 32768
#define SS    196608                 // scores 128 x 65 f32
#define SX    (SS + 128 * 65 * 4)
#define SMEM_KNN (SX + 512)

#define ISSUE_CHUNK(cc) do {                                                   \
    int _c = (cc);                                                             \
    if (_c < 256) {                                                            \
        int _tile = tbase + (_c >> 2);                                         \
        int _kc = _c & 3;                                                      \
        const uint4* _ds = (const uint4*)(g_dbf + (size_t)_tile * 128 * DP);   \
        _Pragma("unroll")                                                      \
        for (int _i = 0; _i < 8; _i++) {                                       \
            int _idx = _i * 256 + tid;                                         \
            int _n = _idx >> 4, _c16 = _idx & 15;                              \
            const uint4* _src = _ds + _n * 64 + _kc * 16 + _c16;               \
            uint32_t _dst = sbase + SB + (_c & 1) * 32768 +                    \
                            (((_n << 4) + (_c16 ^ (_n & 7))) << 4);            \
            CP_ASYNC16(_dst, _src);                                            \
        }                                                                      \
    }                                                                          \
    CP_COMMIT();                                                               \
} while (0)

__global__ void __launch_bounds__(256) knn_mma() {
    extern __shared__ char sm[];
    float* Ssc  = (float*)(sm + SS);
    float* sxnh = (float*)(sm + SX);
    uint32_t sbase = s2u(sm);
    int tid = threadIdx.x;
    int w = tid >> 5, l = tid & 31;
    int wm = w >> 2, wn = w & 3;
    int srow = tid & 127, shalf = tid >> 7;

    for (int u = blockIdx.x; u < UNITS; u += NWORK) {
        int qtile = u >> 4;
        int split = u & 15;
        int qb = qtile * 128;
        int tbase = split * 64;

        __syncthreads();   // prior unit's smem fully consumed

        // prologue: chunks 0,1 in flight while A loads
        ISSUE_CHUNK(0);
        ISSUE_CHUNK(1);

        {   // A (queries) swizzled load
            const uint4* src = (const uint4*)(g_qbf + (size_t)qb * DP);
            #pragma unroll 4
            for (int i = 0; i < 32; i++) {
                int idx = i * 256 + tid;
                int r = idx >> 6, c = idx & 63;
                uint4 v = src[(size_t)r * 64 + c];
                *(uint4*)(sm + SA + (((r << 6) + (c ^ (r & 7))) << 4)) = v;
            }
        }

        float ts[CAP];
        int   ti[CAP];
        #pragma unroll
        for (int r = 0; r < CAP; r++) { ts[r] = -CUDART_INF_F; ti[r] = 0; }

        float acc[4][4][4];

        for (int c = 0; c < 256; c++) {
            CP_WAIT1();
            __syncthreads();
            int kc = c & 3;
            int nb = (tbase + (c >> 2)) * 128;
            if (kc == 0) {
                #pragma unroll
                for (int mt = 0; mt < 4; mt++)
                    #pragma unroll
                    for (int nt = 0; nt < 4; nt++)
                        #pragma unroll
                        for (int rr = 0; rr < 4; rr++) acc[mt][nt][rr] = 0.f;
                if (tid < 128) sxnh[tid] = g_xnh[nb + tid];
            }
            uint32_t Bcur = sbase + SB + (c & 1) * 32768;
            #pragma unroll
            for (int ks = 0; ks < 8; ks++) {
                uint32_t a[4][4], b[4][2];
                #pragma unroll
                for (int mt = 0; mt < 4; mt++) {
                    int r = wm * 64 + mt * 16 + (l & 15);
                    int ca = kc * 16 + ks * 2 + (l >> 4);
                    uint32_t ad = sbase + SA + (((r << 6) + (ca ^ (r & 7))) << 4);
                    LDMATRIX_X4(a[mt], ad);
                }
                #pragma unroll
                for (int p2 = 0; p2 < 2; p2++) {
                    int n = wn * 32 + p2 * 16 + ((l >> 4) & 1) * 8 + (l & 7);
                    int cb2 = ks * 2 + ((l >> 3) & 1);
                    uint32_t ad = Bcur + (((n << 4) + (cb2 ^ (n & 7))) << 4);
                    uint32_t r4[4];
                    LDMATRIX_X4(r4, ad);
                    b[p2 * 2 + 0][0] = r4[0]; b[p2 * 2 + 0][1] = r4[1];
                    b[p2 * 2 + 1][0] = r4[2]; b[p2 * 2 + 1][1] = r4[3];
                }
                #pragma unroll
                for (int mt = 0; mt < 4; mt++)
                    #pragma unroll
                    for (int nt = 0; nt < 4; nt++)
                        MMA16816(acc[mt][nt], a[mt], b[nt]);
            }
            __syncthreads();
            ISSUE_CHUNK(c + 2);

            if (kc == 3) {
                // Epilogue: two n-half passes through the 128x65 score pane
                #pragma unroll
                for (int p = 0; p < 2; p++) {
                    if ((wn >> 1) == p) {
                        int nloc = (wn & 1) * 32;
                        #pragma unroll
                        for (int mt = 0; mt < 4; mt++)
                            #pragma unroll
                            for (int nt = 0; nt < 4; nt++) {
                                int r = wm * 64 + mt * 16 + (l >> 2);
                                int cb = nloc + nt * 8 + (l & 3) * 2;
                                int gc = p * 64 + cb;
                                Ssc[r * 65 + cb]           = acc[mt][nt][0] - sxnh[gc];
                                Ssc[r * 65 + cb + 1]       = acc[mt][nt][1] - sxnh[gc + 1];
                                Ssc[(r + 8) * 65 + cb]     = acc[mt][nt][2] - sxnh[gc];
                                Ssc[(r + 8) * 65 + cb + 1] = acc[mt][nt][3] - sxnh[gc + 1];
                            }
                    }
                    __syncthreads();
                    int cb = shalf * 32;
                    #pragma unroll 8
                    for (int cc = 0; cc < 32; cc++) {
                        float s = Ssc[srow * 65 + cb + cc];
                        if (s > ts[CAP - 1]) {
                            ts[CAP - 1] = s; ti[CAP - 1] = nb + p * 64 + cb + cc;
                            #pragma unroll
                            for (int r = CAP - 1; r > 0; r--) {
                                if (ts[r] > ts[r - 1]) {
                                    float tv = ts[r]; ts[r] = ts[r - 1]; ts[r - 1] = tv;
                                    int   tt = ti[r]; ti[r] = ti[r - 1]; ti[r - 1] = tt;
                                }
                            }
                        }
                    }
                    __syncthreads();
                }
            }
        }

        // Unit end: merge the two half-lists per row, store with scores
        float* msc = Ssc;
        int*   mix = (int*)(sm + SB);   // pipeline drained
        #pragma unroll
        for (int r = 0; r < CAP; r++) {
            msc[tid * CAP + r] = ts[r];
            mix[tid * CAP + r] = ti[r];
        }
        __syncthreads();
        if (tid < 128) {
            size_t base = ((size_t)(qb + tid) * SPLIT + split) * CAP;
            int i0 = 0, i1 = 0;
            #pragma unroll
            for (int r = 0; r < CAP; r++) {
                float s0 = msc[tid * CAP + i0];
                float s1 = msc[(tid + 128) * CAP + i1];
                bool take0 = (s0 >= s1);
                g_part_s[base + r] = take0 ? s0 : s1;
                g_part_i[base + r] = take0 ? mix[tid * CAP + i0]
                                           : mix[(tid + 128) * CAP + i1];
                if (take0) i0++; else i1++;
            }
        }
    }
}

// ---------------- K5: merge 16 per-split lists -> global top-16 ----------------
__global__ void merge_kernel() {
    int q = blockIdx.x * 256 + threadIdx.x;
    const float* ps = g_part_s + (size_t)q * SPLIT * CAP;
    const int*   pi = g_part_i + (size_t)q * SPLIT * CAP;
    float ts[CAP];
    int   ti[CAP];
    #pragma unroll
    for (int r = 0; r < CAP; r++) { ts[r] = -CUDART_INF_F; ti[r] = 0x7fffffff; }
    for (int k = 0; k < SPLIT * CAP; k++) {
        float s = ps[k];
        int ix = pi[k];
        if (s > ts[CAP - 1] || (s == ts[CAP - 1] && ix < ti[CAP - 1])) {
            ts[CAP - 1] = s; ti[CAP - 1] = ix;
            #pragma unroll
            for (int r = CAP - 1; r > 0; r--) {
                if (ts[r] > ts[r - 1] ||
                    (ts[r] == ts[r - 1] && ti[r] < ti[r - 1])) {
                    float tv = ts[r]; ts[r] = ts[r - 1]; ts[r - 1] = tv;
                    int   tt = ti[r]; ti[r] = ti[r - 1]; ti[r - 1] = tt;
                }
            }
        }
    }
    #pragma unroll
    for (int r = 0; r < CAP; r++)
        g_cand[(size_t)q * CAP + r] = ti[r];
}

// -------- K6: refine — reference-arithmetic emulation over 16 candidates ----
__global__ void __launch_bounds__(128) refine_kernel(const float* __restrict__ Dm,
                                                     float* __restrict__ out) {
    __shared__ float qs[4][DP];
    int qb = blockIdx.x * 4;
    int w = threadIdx.x >> 5;
    int lane = threadIdx.x & 31;
    int q = qb + w;

    for (int i = threadIdx.x; i < 4 * DP / 4; i += 128) {
        int qr = i / (DP / 4), c4 = i % (DP / 4);
        *(float4*)&qs[qr][c4 * 4] =
            *(const float4*)(g_query + (size_t)(qb + qr) * DP + c4 * 4);
    }
    __syncthreads();

    float s = 0.f;
    #pragma unroll
    for (int u = 0; u < 16; u++) {
        int j = lane + u * 32;
        if (j < DDIM) {
            float v = qs[w][j];
            s = __fadd_rn(s, __fmul_rn(v, v));
        }
    }
    #pragma unroll
    for (int o = 16; o; o >>= 1)
        s = __fadd_rn(s, __shfl_down_sync(0xffffffffu, s, o));
    float qn = __shfl_sync(0xffffffffu, s, 0);

    float dzc = CUDART_INF_F;
    int   idxc = 0;
    if (lane < CAP) {
        idxc = g_cand[(size_t)q * CAP + lane];
        const float* drow = Dm + (size_t)idxc * DDIM;
        float dot = 0.f;
        for (int k = 0; k < DDIM; k++)
            dot = __fmaf_rn(qs[w][k], drow[k], dot);
        float xn = g_xn_emu[idxc];
        float t1 = __fadd_rn(qn, xn);
        dzc = __fsub_rn(t1, __fmul_rn(2.0f, dot));
    }

    float dz[CAP];
    int   ci[CAP];
    #pragma unroll
    for (int c = 0; c < CAP; c++) {
        dz[c] = __shfl_sync(0xffffffffu, dzc, c);
        ci[c] = __shfl_sync(0xffffffffu, idxc, c);
    }
    if (lane == 0) {
        #pragma unroll
        for (int r = 0; r < TOPK; r++) {
            int best = r;
            #pragma unroll
            for (int c = 0; c < CAP; c++) {
                if (c <= r) continue;
                if (dz[c] < dz[best] || (dz[c] == dz[best] && ci[c] < ci[best]))
                    best = c;
            }
            float td = dz[r]; dz[r] = dz[best]; dz[best] = td;
            int   tc = ci[r]; ci[r] = ci[best]; ci[best] = tc;
            out[(size_t)q * TOPK + r] = (float)ci[r];
        }
    }
}

extern "C" void kernel_launch(void* const* d_in, const int* in_sizes, int n_in,
                              void* d_out, int out_size) {
    const float* E  = nullptr;
    const float* P  = nullptr;
    const float* Dm = nullptr;
    for (int i = 0; i < n_in; i++) {
        long long sz = (long long)in_sizes[i];
        if (sz == (long long)NQ * NPIX)        E  = (const float*)d_in[i];
        else if (sz == (long long)NPIX * DDIM) P  = (const float*)d_in[i];
        else if (sz == (long long)ND * DDIM)   Dm = (const float*)d_in[i];
    }
    if (!E || !P || !Dm) {
        int idx[16];
        int m = n_in < 16 ? n_in : 16;
        for (int i = 0; i < m; i++) idx[i] = i;
        for (int a = 0; a < m; a++)
            for (int b = a + 1; b < m; b++)
                if ((long long)in_sizes[idx[b]] > (long long)in_sizes[idx[a]]) {
                    int tmp = idx[a]; idx[a] = idx[b]; idx[b] = tmp;
                }
        if (m >= 3) { Dm = (const float*)d_in[idx[0]];
                      E  = (const float*)d_in[idx[1]];
                      P  = (const float*)d_in[idx[2]]; }
    }
    if (!E || !P || !Dm) return;

    float* out = (float*)d_out;

    static bool attr_set = false;
    if (!attr_set) {
        cudaFuncSetAttribute(queryemu_kernel,
                             cudaFuncAttributeMaxDynamicSharedMemorySize,
                             KCH * 36 * (int)sizeof(float));
        cudaFuncSetAttribute(knn_mma,
                             cudaFuncAttributeMaxDynamicSharedMemorySize,
                             SMEM_KNN);
        attr_set = true;
    }

    rowmean_kernel<<<NQ, 256>>>(E);
    dictprep_kernel<<<ND / 4, 128>>>(Dm);
    queryemu_kernel<<<NQ / 32, 512, KCH * 36 * sizeof(float)>>>(E, P);
    qbf_kernel<<<(int)(((size_t)NQ * DP + 255) / 256), 256>>>();
    knn_mma<<<NWORK, 256, SMEM_KNN>>>();
    merge_kernel<<<NQ / 256, 256>>>();
    refine_kernel<<<NQ / 4, 128>>>(Dm, out);
}

// round 16
// speedup vs baseline: 1.8964x; 1.2039x over previous
#include <cuda_runtime.h>
#include <cuda_bf16.h>
#include <math_constants.h>
#include <cstdint>

#define NQ   16384
#define NPIX 3600
#define ND   131072
#define DDIM 500
#define DP   512   // padded K
#define TOPK 8
#define CAP  16

// ---------------- scratch (__device__ globals; no allocation) ----------------
__device__ float          g_query[(size_t)NQ * DP];   // emulated ref query (f32)
__device__ __nv_bfloat16  g_qbf[(size_t)NQ * DP];     // bf16 query (pass-1)
__device__ __nv_bfloat16  g_dbf[(size_t)ND * DP];     // bf16 dict  (pass-1)
__device__ float          g_xn_emu[ND];               // emulated fp32 ||d||^2
__device__ float          g_xnh[ND];                  // 0.5*||d||^2 (pass-1)
__device__ float          g_mean32[NQ];
__device__ int            g_cand[(size_t)NQ * CAP];

__device__ __forceinline__ uint32_t s2u(const void* p) {
    uint32_t a;
    asm("{ .reg .u64 t; cvta.to.shared.u64 t, %1; cvt.u32.u64 %0, t; }"
        : "=r"(a) : "l"(p));
    return a;
}

#define LDMATRIX_X4(r, addr)                                                   \
    asm volatile("ldmatrix.sync.aligned.m8n8.x4.shared.b16 {%0,%1,%2,%3}, [%4];" \
        : "=r"((r)[0]), "=r"((r)[1]), "=r"((r)[2]), "=r"((r)[3]) : "r"(addr))
#define MMA16816(d, a, b)                                                      \
    asm volatile("mma.sync.aligned.m16n8k16.row.col.f32.bf16.bf16.f32 "        \
        "{%0,%1,%2,%3}, {%4,%5,%6,%7}, {%8,%9}, {%0,%1,%2,%3};"                \
        : "+f"((d)[0]), "+f"((d)[1]), "+f"((d)[2]), "+f"((d)[3])               \
        : "r"((a)[0]), "r"((a)[1]), "r"((a)[2]), "r"((a)[3]),                  \
          "r"((b)[0]), "r"((b)[1]))

// ---------------- K0: row means (fp64) ----------------
__global__ void rowmean_kernel(const float* __restrict__ E) {
    int row = blockIdx.x;
    const float* r = E + (size_t)row * NPIX;
    double s = 0.0;
    for (int i = threadIdx.x; i < NPIX; i += 256) s += (double)r[i];
    __shared__ double sh[8];
    #pragma unroll
    for (int o = 16; o; o >>= 1) s += __shfl_down_sync(0xffffffffu, s, o);
    if ((threadIdx.x & 31) == 0) sh[threadIdx.x >> 5] = s;
    __syncthreads();
    if (threadIdx.x == 0) {
        double t = 0.0;
        #pragma unroll
        for (int w = 0; w < 8; w++) t += sh[w];
        g_mean32[row] = __fdiv_rn((float)t, (float)NPIX);
    }
}

// ---------------- K1: dict prep: bf16 + emulated fp32 norms ----------------
__global__ void dictprep_kernel(const float* __restrict__ Dm) {
    int row = blockIdx.x * 4 + (threadIdx.x >> 5);
    int lane = threadIdx.x & 31;
    const float* src = Dm + (size_t)row * DDIM;
    __nv_bfloat16* dbf = g_dbf + (size_t)row * DP;
    float s = 0.f;
    #pragma unroll
    for (int u = 0; u < 16; u++) {
        int j = lane + u * 32;
        float v = (j < DDIM) ? src[j] : 0.f;
        dbf[j] = __float2bfloat16(v);
        if (j < DDIM) s = __fadd_rn(s, __fmul_rn(v, v));
    }
    #pragma unroll
    for (int o = 16; o; o >>= 1)
        s = __fadd_rn(s, __shfl_down_sync(0xffffffffu, s, o));
    if (lane == 0) {
        g_xn_emu[row] = s;
        g_xnh[row] = 0.5f * s;
    }
}

// ---- K2: emulated query GEMM, 32 q/block, chunked staging (exact k order) ----
// Also emits the bf16 copy (fused; removes the separate qbf kernel).
#define KCH 600
__global__ void __launch_bounds__(512) queryemu_kernel(const float* __restrict__ E,
                                                       const float* __restrict__ P) {
    extern __shared__ float cs[];   // [KCH][36]
    __shared__ float ms[32];
    int qb = blockIdx.x * 32;
    int t = threadIdx.x;
    if (t < 32) ms[t] = g_mean32[qb + t];
    __syncthreads();

    float a[32];
    #pragma unroll
    for (int q = 0; q < 32; q++) a[q] = 0.f;

    for (int k0 = 0; k0 < NPIX; k0 += KCH) {
        __syncthreads();
        for (int q = 0; q < 32; q++) {
            float m = ms[q];
            const float* erow = E + (size_t)(qb + q) * NPIX + k0;
            for (int k = t; k < KCH; k += 512)
                cs[k * 36 + q] = __fsub_rn(erow[k], m);
        }
        __syncthreads();
        if (t < DDIM) {
            const float* p = P + (size_t)k0 * DDIM + t;
            for (int k = 0; k < KCH; k++) {
                float pv = p[(size_t)k * DDIM];
                const float4* c4 = (const float4*)(cs + k * 36);
                #pragma unroll
                for (int j = 0; j < 8; j++) {
                    float4 cv = c4[j];
                    a[j * 4 + 0] = __fmaf_rn(cv.x, pv, a[j * 4 + 0]);
                    a[j * 4 + 1] = __fmaf_rn(cv.y, pv, a[j * 4 + 1]);
                    a[j * 4 + 2] = __fmaf_rn(cv.z, pv, a[j * 4 + 2]);
                    a[j * 4 + 3] = __fmaf_rn(cv.w, pv, a[j * 4 + 3]);
                }
            }
        }
    }
    if (t < DDIM) {
        #pragma unroll
        for (int q = 0; q < 32; q++) {
            g_query[(size_t)(qb + q) * DP + t] = a[q];
            g_qbf[(size_t)(qb + q) * DP + t] = __float2bfloat16(a[q]);
        }
    } else {
        #pragma unroll
        for (int q = 0; q < 32; q++) {
            g_query[(size_t)(qb + q) * DP + t] = 0.f;
            g_qbf[(size_t)(qb + q) * DP + t] = __float2bfloat16(0.f);
        }
    }
}

// ------------- K3: HMMA bf16 pass-1: 512 threads (4 warps/SMSP) -------------
// 128 CTAs x 512 thr (16 warps: wm=w>>2 in [0,4), wn=w&3 in [0,4)).
// Warp tile 32m x 32n (mt 2 x nt 4). Same fragment algebra as the verified
// 256-thread version; only the warp grid scales.
#define SA    0
#define SB    131072                 // 2 x 32768
#define SS    196608                 // scores 128 x 65 f32
#define SX    (SS + 128 * 65 * 4)
#define SMEM_KNN (SX + 512)

__global__ void __launch_bounds__(512) knn_mma() {
    extern __shared__ char sm[];
    float* Ssc  = (float*)(sm + SS);
    float* sxnh = (float*)(sm + SX);
    uint32_t sbase = s2u(sm);
    int tid = threadIdx.x;
    int w = tid >> 5, l = tid & 31;
    int wm = w >> 2, wn = w & 3;
    int qb = blockIdx.x * 128;

    // Load A (queries) with swizzle: 8192 16B-chunks, 16/thread
    {
        const uint4* src = (const uint4*)(g_qbf + (size_t)qb * DP);
        #pragma unroll 4
        for (int i = 0; i < 16; i++) {
            int idx = i * 512 + tid;
            int r = idx >> 6, c = idx & 63;
            uint4 v = src[(size_t)r * 64 + c];
            *(uint4*)(sm + SA + (((r << 6) + (c ^ (r & 7))) << 4)) = v;
        }
    }

    float ts[CAP];
    int   ti[CAP];
    #pragma unroll
    for (int r = 0; r < CAP; r++) { ts[r] = -CUDART_INF_F; ti[r] = 0; }

    int srow = tid & 127, sq = tid >> 7;   // 4 scanners per query row

    for (int t = 0; t < ND / 128; t++) {
        int nb = t * 128;
        if (tid < 128) sxnh[tid] = g_xnh[nb + tid];

        const uint4* dsrc = (const uint4*)(g_dbf + (size_t)nb * DP);
        uint4 pre[4];
        // kc0 chunk -> buf 0 (2048 16B-chunks, 4/thread)
        #pragma unroll
        for (int i = 0; i < 4; i++) {
            int idx = i * 512 + tid;
            int n = idx >> 4, c = idx & 15;
            pre[i] = dsrc[(size_t)(n << 6) + c];
        }
        #pragma unroll
        for (int i = 0; i < 4; i++) {
            int idx = i * 512 + tid;
            int n = idx >> 4, c = idx & 15;
            *(uint4*)(sm + SB + (((n << 4) + (c ^ (n & 7))) << 4)) = pre[i];
        }
        __syncthreads();

        float acc[2][4][4];
        #pragma unroll
        for (int mt = 0; mt < 2; mt++)
            #pragma unroll
            for (int nt = 0; nt < 4; nt++)
                #pragma unroll
                for (int rr = 0; rr < 4; rr++) acc[mt][nt][rr] = 0.f;

        #pragma unroll
        for (int kc = 0; kc < 4; kc++) {
            if (kc < 3) {
                #pragma unroll
                for (int i = 0; i < 4; i++) {
                    int idx = i * 512 + tid;
                    int n = idx >> 4, c = idx & 15;
                    pre[i] = dsrc[(size_t)(n << 6) + ((kc + 1) << 4) + c];
                }
            }
            uint32_t Bcur = sbase + SB + (kc & 1) * 32768;
            #pragma unroll
            for (int ks = 0; ks < 8; ks++) {
                uint32_t a[2][4], b[4][2];
                #pragma unroll
                for (int mt = 0; mt < 2; mt++) {
                    int r = wm * 32 + mt * 16 + (l & 15);
                    int ca = kc * 16 + ks * 2 + (l >> 4);
                    uint32_t ad = sbase + SA + (((r << 6) + (ca ^ (r & 7))) << 4);
                    LDMATRIX_X4(a[mt], ad);
                }
                #pragma unroll
                for (int p2 = 0; p2 < 2; p2++) {
                    int n = wn * 32 + p2 * 16 + ((l >> 4) & 1) * 8 + (l & 7);
                    int cb2 = ks * 2 + ((l >> 3) & 1);
                    uint32_t ad = Bcur + (((n << 4) + (cb2 ^ (n & 7))) << 4);
                    uint32_t r4[4];
                    LDMATRIX_X4(r4, ad);
                    b[p2 * 2 + 0][0] = r4[0]; b[p2 * 2 + 0][1] = r4[1];
                    b[p2 * 2 + 1][0] = r4[2]; b[p2 * 2 + 1][1] = r4[3];
                }
                #pragma unroll
                for (int mt = 0; mt < 2; mt++)
                    #pragma unroll
                    for (int nt = 0; nt < 4; nt++)
                        MMA16816(acc[mt][nt], a[mt], b[nt]);
            }
            __syncthreads();
            if (kc < 3) {
                #pragma unroll
                for (int i = 0; i < 4; i++) {
                    int idx = i * 512 + tid;
                    int n = idx >> 4, c = idx & 15;
                    *(uint4*)(sm + SB + ((kc + 1) & 1) * 32768 +
                              (((n << 4) + (c ^ (n & 7))) << 4)) = pre[i];
                }
                __syncthreads();
            }
        }

        // Epilogue: two n-half passes (64 cols each) through 128x65 pane
        #pragma unroll
        for (int p = 0; p < 2; p++) {
            if ((wn >> 1) == p) {
                int nloc = (wn & 1) * 32;
                #pragma unroll
                for (int mt = 0; mt < 2; mt++)
                    #pragma unroll
                    for (int nt = 0; nt < 4; nt++) {
                        int r = wm * 32 + mt * 16 + (l >> 2);
                        int cb = nloc + nt * 8 + (l & 3) * 2;
                        int gc = p * 64 + cb;
                        Ssc[r * 65 + cb]           = acc[mt][nt][0] - sxnh[gc];
                        Ssc[r * 65 + cb + 1]       = acc[mt][nt][1] - sxnh[gc + 1];
                        Ssc[(r + 8) * 65 + cb]     = acc[mt][nt][2] - sxnh[gc];
                        Ssc[(r + 8) * 65 + cb + 1] = acc[mt][nt][3] - sxnh[gc + 1];
                    }
            }
            __syncthreads();
            int cb = sq * 16;
            #pragma unroll 8
            for (int cc = 0; cc < 16; cc++) {
                float s = Ssc[srow * 65 + cb + cc];
                if (s > ts[CAP - 1]) {
                    ts[CAP - 1] = s; ti[CAP - 1] = nb + p * 64 + cb + cc;
                    #pragma unroll
                    for (int r = CAP - 1; r > 0; r--) {
                        if (ts[r] > ts[r - 1]) {
                            float tv = ts[r]; ts[r] = ts[r - 1]; ts[r - 1] = tv;
                            int   tt = ti[r]; ti[r] = ti[r - 1]; ti[r - 1] = tt;
                        }
                    }
                }
            }
            __syncthreads();
        }
    }

    // Final: 4-way merge of per-scanner sorted lists -> top-16 per query row.
    // Comparator (score desc, idx asc) reproduces a single sequential scan.
    float* msc = Ssc;                  // 512*16*4 = 32KB fits in score pane
    int*   mix = (int*)(sm + SB);      // 32KB
    #pragma unroll
    for (int r = 0; r < CAP; r++) {
        msc[tid * CAP + r] = ts[r];
        mix[tid * CAP + r] = ti[r];
    }
    __syncthreads();
    if (tid < 128) {
        int ip[4] = {0, 0, 0, 0};
        #pragma unroll
        for (int r = 0; r < CAP; r++) {
            float bs = -CUDART_INF_F;
            int bi = 0x7fffffff, bl = 0;
            #pragma unroll
            for (int j = 0; j < 4; j++) {
                if (ip[j] < CAP) {
                    int off = (tid + j * 128) * CAP + ip[j];
                    float s = msc[off];
                    int ix = mix[off];
                    if (s > bs || (s == bs && ix < bi)) { bs = s; bi = ix; bl = j; }
                }
            }
            g_cand[(size_t)(qb + tid) * CAP + r] = bi;
            ip[bl]++;
        }
    }
}

// -------- K4: refine — reference-arithmetic emulation over 16 candidates ----
__global__ void __launch_bounds__(128) refine_kernel(const float* __restrict__ Dm,
                                                     float* __restrict__ out) {
    __shared__ float qs[4][DP];
    int qb = blockIdx.x * 4;
    int w = threadIdx.x >> 5;
    int lane = threadIdx.x & 31;
    int q = qb + w;

    for (int i = threadIdx.x; i < 4 * DP / 4; i += 128) {
        int qr = i / (DP / 4), c4 = i % (DP / 4);
        *(float4*)&qs[qr][c4 * 4] =
            *(const float4*)(g_query + (size_t)(qb + qr) * DP + c4 * 4);
    }
    __syncthreads();

    float s = 0.f;
    #pragma unroll
    for (int u = 0; u < 16; u++) {
        int j = lane + u * 32;
        if (j < DDIM) {
            float v = qs[w][j];
            s = __fadd_rn(s, __fmul_rn(v, v));
        }
    }
    #pragma unroll
    for (int o = 16; o; o >>= 1)
        s = __fadd_rn(s, __shfl_down_sync(0xffffffffu, s, o));
    float qn = __shfl_sync(0xffffffffu, s, 0);

    float dzc = CUDART_INF_F;
    int   idxc = 0;
    if (lane < CAP) {
        idxc = g_cand[(size_t)q * CAP + lane];
        const float* drow = Dm + (size_t)idxc * DDIM;
        float dot = 0.f;
        for (int k = 0; k < DDIM; k++)
            dot = __fmaf_rn(qs[w][k], drow[k], dot);
        float xn = g_xn_emu[idxc];
        float t1 = __fadd_rn(qn, xn);
        dzc = __fsub_rn(t1, __fmul_rn(2.0f, dot));
    }

    float dz[CAP];
    int   ci[CAP];
    #pragma unroll
    for (int c = 0; c < CAP; c++) {
        dz[c] = __shfl_sync(0xffffffffu, dzc, c);
        ci[c] = __shfl_sync(0xffffffffu, idxc, c);
    }
    if (lane == 0) {
        #pragma unroll
        for (int r = 0; r < TOPK; r++) {
            int best = r;
            #pragma unroll
            for (int c = 0; c < CAP; c++) {
                if (c <= r) continue;
                if (dz[c] < dz[best] || (dz[c] == dz[best] && ci[c] < ci[best]))
                    best = c;
            }
            float td = dz[r]; dz[r] = dz[best]; dz[best] = td;
            int   tc = ci[r]; ci[r] = ci[best]; ci[best] = tc;
            out[(size_t)q * TOPK + r] = (float)ci[r];
        }
    }
}

extern "C" void kernel_launch(void* const* d_in, const int* in_sizes, int n_in,
                              void* d_out, int out_size) {
    const float* E  = nullptr;
    const float* P  = nullptr;
    const float* Dm = nullptr;
    for (int i = 0; i < n_in; i++) {
        long long sz = (long long)in_sizes[i];
        if (sz == (long long)NQ * NPIX)        E  = (const float*)d_in[i];
        else if (sz == (long long)NPIX * DDIM) P  = (const float*)d_in[i];
        else if (sz == (long long)ND * DDIM)   Dm = (const float*)d_in[i];
    }
    if (!E || !P || !Dm) {
        int idx[16];
        int m = n_in < 16 ? n_in : 16;
        for (int i = 0; i < m; i++) idx[i] = i;
        for (int a = 0; a < m; a++)
            for (int b = a + 1; b < m; b++)
                if ((long long)in_sizes[idx[b]] > (long long)in_sizes[idx[a]]) {
                    int tmp = idx[a]; idx[a] = idx[b]; idx[b] = tmp;
                }
        if (m >= 3) { Dm = (const float*)d_in[idx[0]];
                      E  = (const float*)d_in[idx[1]];
                      P  = (const float*)d_in[idx[2]]; }
    }
    if (!E || !P || !Dm) return;

    float* out = (float*)d_out;

    static bool attr_set = false;
    if (!attr_set) {
        cudaFuncSetAttribute(queryemu_kernel,
                             cudaFuncAttributeMaxDynamicSharedMemorySize,
                             KCH * 36 * (int)sizeof(float));
        cudaFuncSetAttribute(knn_mma,
                             cudaFuncAttributeMaxDynamicSharedMemorySize,
                             SMEM_KNN);
        attr_set = true;
    }

    rowmean_kernel<<<NQ, 256>>>(E);
    dictprep_kernel<<<ND / 4, 128>>>(Dm);
    queryemu_kernel<<<NQ / 32, 512, KCH * 36 * sizeof(float)>>>(E, P);
    knn_mma<<<NQ / 128, 512, SMEM_KNN>>>();
    refine_kernel<<<NQ / 4, 128>>>(Dm, out);
}

// round 17
// speedup vs baseline: 1.9669x; 1.0372x over previous
#include <cuda_runtime.h>
#include <cuda_bf16.h>
#include <math_constants.h>
#include <cstdint>

#define NQ   16384
#define NPIX 3600
#define ND   131072
#define DDIM 500
#define DP   512   // padded K
#define TOPK 8
#define CAP  16

// ---------------- scratch (__device__ globals; no allocation) ----------------
__device__ float          g_query[(size_t)NQ * DP];   // emulated ref query (f32)
__device__ __nv_bfloat16  g_qbf[(size_t)NQ * DP];     // bf16 query (pass-1)
__device__ __nv_bfloat16  g_dbf[(size_t)ND * DP];     // bf16 dict  (pass-1)
__device__ float          g_xn_emu[ND];               // emulated fp32 ||d||^2
__device__ float          g_xnh[ND];                  // 0.5*||d||^2 (pass-1)
__device__ float          g_mean32[NQ];
__device__ int            g_cand[(size_t)NQ * CAP];

__device__ __forceinline__ uint32_t s2u(const void* p) {
    uint32_t a;
    asm("{ .reg .u64 t; cvta.to.shared.u64 t, %1; cvt.u32.u64 %0, t; }"
        : "=r"(a) : "l"(p));
    return a;
}

#define LDMATRIX_X4(r, addr)                                                   \
    asm volatile("ldmatrix.sync.aligned.m8n8.x4.shared.b16 {%0,%1,%2,%3}, [%4];" \
        : "=r"((r)[0]), "=r"((r)[1]), "=r"((r)[2]), "=r"((r)[3]) : "r"(addr))
#define MMA16816(d, a, b)                                                      \
    asm volatile("mma.sync.aligned.m16n8k16.row.col.f32.bf16.bf16.f32 "        \
        "{%0,%1,%2,%3}, {%4,%5,%6,%7}, {%8,%9}, {%0,%1,%2,%3};"                \
        : "+f"((d)[0]), "+f"((d)[1]), "+f"((d)[2]), "+f"((d)[3])               \
        : "r"((a)[0]), "r"((a)[1]), "r"((a)[2]), "r"((a)[3]),                  \
          "r"((b)[0]), "r"((b)[1]))

// ---------------- K0: row means (fp64) ----------------
__global__ void rowmean_kernel(const float* __restrict__ E) {
    int row = blockIdx.x;
    const float* r = E + (size_t)row * NPIX;
    double s = 0.0;
    for (int i = threadIdx.x; i < NPIX; i += 256) s += (double)r[i];
    __shared__ double sh[8];
    #pragma unroll
    for (int o = 16; o; o >>= 1) s += __shfl_down_sync(0xffffffffu, s, o);
    if ((threadIdx.x & 31) == 0) sh[threadIdx.x >> 5] = s;
    __syncthreads();
    if (threadIdx.x == 0) {
        double t = 0.0;
        #pragma unroll
        for (int w = 0; w < 8; w++) t += sh[w];
        g_mean32[row] = __fdiv_rn((float)t, (float)NPIX);
    }
}

// ---------------- K1: dict prep: bf16 + emulated fp32 norms ----------------
__global__ void dictprep_kernel(const float* __restrict__ Dm) {
    int row = blockIdx.x * 4 + (threadIdx.x >> 5);
    int lane = threadIdx.x & 31;
    const float* src = Dm + (size_t)row * DDIM;
    __nv_bfloat16* dbf = g_dbf + (size_t)row * DP;
    float s = 0.f;
    #pragma unroll
    for (int u = 0; u < 16; u++) {
        int j = lane + u * 32;
        float v = (j < DDIM) ? src[j] : 0.f;
        dbf[j] = __float2bfloat16(v);
        if (j < DDIM) s = __fadd_rn(s, __fmul_rn(v, v));
    }
    #pragma unroll
    for (int o = 16; o; o >>= 1)
        s = __fadd_rn(s, __shfl_down_sync(0xffffffffu, s, o));
    if (lane == 0) {
        g_xn_emu[row] = s;
        g_xnh[row] = 0.5f * s;
    }
}

// ---- K2: emulated query GEMM, 32 q/block, chunked staging (exact k order) ----
#define KCH 600
__global__ void __launch_bounds__(512) queryemu_kernel(const float* __restrict__ E,
                                                       const float* __restrict__ P) {
    extern __shared__ float cs[];   // [KCH][36]
    __shared__ float ms[32];
    int qb = blockIdx.x * 32;
    int t = threadIdx.x;
    if (t < 32) ms[t] = g_mean32[qb + t];
    __syncthreads();

    float a[32];
    #pragma unroll
    for (int q = 0; q < 32; q++) a[q] = 0.f;

    for (int k0 = 0; k0 < NPIX; k0 += KCH) {
        __syncthreads();
        for (int q = 0; q < 32; q++) {
            float m = ms[q];
            const float* erow = E + (size_t)(qb + q) * NPIX + k0;
            for (int k = t; k < KCH; k += 512)
                cs[k * 36 + q] = __fsub_rn(erow[k], m);
        }
        __syncthreads();
        if (t < DDIM) {
            const float* p = P + (size_t)k0 * DDIM + t;
            for (int k = 0; k < KCH; k++) {
                float pv = p[(size_t)k * DDIM];
                const float4* c4 = (const float4*)(cs + k * 36);
                #pragma unroll
                for (int j = 0; j < 8; j++) {
                    float4 cv = c4[j];
                    a[j * 4 + 0] = __fmaf_rn(cv.x, pv, a[j * 4 + 0]);
                    a[j * 4 + 1] = __fmaf_rn(cv.y, pv, a[j * 4 + 1]);
                    a[j * 4 + 2] = __fmaf_rn(cv.z, pv, a[j * 4 + 2]);
                    a[j * 4 + 3] = __fmaf_rn(cv.w, pv, a[j * 4 + 3]);
                }
            }
        }
    }
    if (t < DDIM) {
        #pragma unroll
        for (int q = 0; q < 32; q++) {
            g_query[(size_t)(qb + q) * DP + t] = a[q];
            g_qbf[(size_t)(qb + q) * DP + t] = __float2bfloat16(a[q]);
        }
    } else {
        #pragma unroll
        for (int q = 0; q < 32; q++) {
            g_query[(size_t)(qb + q) * DP + t] = 0.f;
            g_qbf[(size_t)(qb + q) * DP + t] = __float2bfloat16(0.f);
        }
    }
}

// ------------- K3: HMMA bf16 pass-1, 64-query CTAs, 2 CTAs/SM -------------
// 256 CTAs x 256 thr (8 warps: wm=w>>2 in [0,2), wn=w&3 in [0,4)).
// A: [64 q][512 k] bf16 smem swizzled (64KB). B: 2 x 16KB (128n x 64k chunks).
// Warp tile 32m x 32n (verified R16 fragment algebra; only grid scales).
#define SA    0
#define SB    65536                  // 2 x 16384
#define SS    98304                  // scores 64 x 65 f32 = 16640
#define SX    (SS + 64 * 65 * 4)     // 114944
#define SMEM_KNN (SX + 512)          // 115456 -> 2 CTAs/SM (230912 <= 233472)

__global__ void __launch_bounds__(256, 2) knn_mma() {
    extern __shared__ char sm[];
    float* Ssc  = (float*)(sm + SS);
    float* sxnh = (float*)(sm + SX);
    uint32_t sbase = s2u(sm);
    int tid = threadIdx.x;
    int w = tid >> 5, l = tid & 31;
    int wm = w >> 2, wn = w & 3;
    int qb = blockIdx.x * 64;

    // Load A (64 query rows) with swizzle: 4096 16B-chunks, 16/thread
    {
        const uint4* src = (const uint4*)(g_qbf + (size_t)qb * DP);
        #pragma unroll 4
        for (int i = 0; i < 16; i++) {
            int idx = i * 256 + tid;
            int r = idx >> 6, c = idx & 63;
            uint4 v = src[(size_t)r * 64 + c];
            *(uint4*)(sm + SA + (((r << 6) + (c ^ (r & 7))) << 4)) = v;
        }
    }

    float ts[CAP];
    int   ti[CAP];
    #pragma unroll
    for (int r = 0; r < CAP; r++) { ts[r] = -CUDART_INF_F; ti[r] = 0; }

    int srow = tid & 63, sq = tid >> 6;   // 4 scanners per query row

    for (int t = 0; t < ND / 128; t++) {
        int nb = t * 128;
        if (tid < 128) sxnh[tid] = g_xnh[nb + tid];

        const uint4* dsrc = (const uint4*)(g_dbf + (size_t)nb * DP);
        uint4 pre[4];
        // kc0 chunk (64k) -> buf 0 : 1024 16B-chunks, 4/thread
        #pragma unroll
        for (int i = 0; i < 4; i++) {
            int idx = i * 256 + tid;
            int n = idx >> 3, c = idx & 7;
            pre[i] = dsrc[(size_t)(n << 6) + c];
        }
        #pragma unroll
        for (int i = 0; i < 4; i++) {
            int idx = i * 256 + tid;
            int n = idx >> 3, c = idx & 7;
            *(uint4*)(sm + SB + (((n << 3) + (c ^ (n & 7))) << 4)) = pre[i];
        }
        __syncthreads();

        float acc[2][4][4];
        #pragma unroll
        for (int mt = 0; mt < 2; mt++)
            #pragma unroll
            for (int nt = 0; nt < 4; nt++)
                #pragma unroll
                for (int rr = 0; rr < 4; rr++) acc[mt][nt][rr] = 0.f;

        #pragma unroll
        for (int kc = 0; kc < 8; kc++) {
            if (kc < 7) {   // prefetch next 64k chunk
                #pragma unroll
                for (int i = 0; i < 4; i++) {
                    int idx = i * 256 + tid;
                    int n = idx >> 3, c = idx & 7;
                    pre[i] = dsrc[(size_t)(n << 6) + ((kc + 1) << 3) + c];
                }
            }
            uint32_t Bcur = sbase + SB + (kc & 1) * 16384;
            #pragma unroll
            for (int ks = 0; ks < 4; ks++) {
                uint32_t a[2][4], b[4][2];
                #pragma unroll
                for (int mt = 0; mt < 2; mt++) {
                    int r = wm * 32 + mt * 16 + (l & 15);
                    int ca = kc * 8 + ks * 2 + (l >> 4);
                    uint32_t ad = sbase + SA + (((r << 6) + (ca ^ (r & 7))) << 4);
                    LDMATRIX_X4(a[mt], ad);
                }
                #pragma unroll
                for (int p2 = 0; p2 < 2; p2++) {
                    int n = wn * 32 + p2 * 16 + ((l >> 4) & 1) * 8 + (l & 7);
                    int cb2 = ks * 2 + ((l >> 3) & 1);
                    uint32_t ad = Bcur + (((n << 3) + (cb2 ^ (n & 7))) << 4);
                    uint32_t r4[4];
                    LDMATRIX_X4(r4, ad);
                    b[p2 * 2 + 0][0] = r4[0]; b[p2 * 2 + 0][1] = r4[1];
                    b[p2 * 2 + 1][0] = r4[2]; b[p2 * 2 + 1][1] = r4[3];
                }
                #pragma unroll
                for (int mt = 0; mt < 2; mt++)
                    #pragma unroll
                    for (int nt = 0; nt < 4; nt++)
                        MMA16816(acc[mt][nt], a[mt], b[nt]);
            }
            __syncthreads();
            if (kc < 7) {
                #pragma unroll
                for (int i = 0; i < 4; i++) {
                    int idx = i * 256 + tid;
                    int n = idx >> 3, c = idx & 7;
                    *(uint4*)(sm + SB + ((kc + 1) & 1) * 16384 +
                              (((n << 3) + (c ^ (n & 7))) << 4)) = pre[i];
                }
                __syncthreads();
            }
        }

        // Epilogue: two n-half passes (64 cols each) through 64x65 pane
        #pragma unroll
        for (int p = 0; p < 2; p++) {
            if ((wn >> 1) == p) {
                int nloc = (wn & 1) * 32;
                #pragma unroll
                for (int mt = 0; mt < 2; mt++)
                    #pragma unroll
                    for (int nt = 0; nt < 4; nt++) {
                        int r = wm * 32 + mt * 16 + (l >> 2);
                        int cb = nloc + nt * 8 + (l & 3) * 2;
                        int gc = p * 64 + cb;
                        Ssc[r * 65 + cb]           = acc[mt][nt][0] - sxnh[gc];
                        Ssc[r * 65 + cb + 1]       = acc[mt][nt][1] - sxnh[gc + 1];
                        Ssc[(r + 8) * 65 + cb]     = acc[mt][nt][2] - sxnh[gc];
                        Ssc[(r + 8) * 65 + cb + 1] = acc[mt][nt][3] - sxnh[gc + 1];
                    }
            }
            __syncthreads();
            int cb = sq * 16;
            #pragma unroll 8
            for (int cc = 0; cc < 16; cc++) {
                float s = Ssc[srow * 65 + cb + cc];
                if (s > ts[CAP - 1]) {
                    ts[CAP - 1] = s; ti[CAP - 1] = nb + p * 64 + cb + cc;
                    #pragma unroll
                    for (int r = CAP - 1; r > 0; r--) {
                        if (ts[r] > ts[r - 1]) {
                            float tv = ts[r]; ts[r] = ts[r - 1]; ts[r - 1] = tv;
                            int   tt = ti[r]; ti[r] = ti[r - 1]; ti[r - 1] = tt;
                        }
                    }
                }
            }
            __syncthreads();
        }
    }

    // Final: 4-way merge of per-scanner sorted lists -> top-16 per query row.
    float* msc = (float*)(sm + SB);          // 256*16*4 = 16KB
    int*   mix = (int*)(sm + SB + 16384);    // 16KB
    #pragma unroll
    for (int r = 0; r < CAP; r++) {
        msc[tid * CAP + r] = ts[r];
        mix[tid * CAP + r] = ti[r];
    }
    __syncthreads();
    if (tid < 64) {
        int ip[4] = {0, 0, 0, 0};
        #pragma unroll
        for (int r = 0; r < CAP; r++) {
            float bs = -CUDART_INF_F;
            int bi = 0x7fffffff, bl = 0;
            #pragma unroll
            for (int j = 0; j < 4; j++) {
                if (ip[j] < CAP) {
                    int off = (tid + j * 64) * CAP + ip[j];
                    float s = msc[off];
                    int ix = mix[off];
                    if (s > bs || (s == bs && ix < bi)) { bs = s; bi = ix; bl = j; }
                }
            }
            g_cand[(size_t)(qb + tid) * CAP + r] = bi;
            ip[bl]++;
        }
    }
}

// -------- K4: refine — reference-arithmetic emulation over 16 candidates ----
__global__ void __launch_bounds__(128) refine_kernel(const float* __restrict__ Dm,
                                                     float* __restrict__ out) {
    __shared__ float qs[4][DP];
    int qb = blockIdx.x * 4;
    int w = threadIdx.x >> 5;
    int lane = threadIdx.x & 31;
    int q = qb + w;

    for (int i = threadIdx.x; i < 4 * DP / 4; i += 128) {
        int qr = i / (DP / 4), c4 = i % (DP / 4);
        *(float4*)&qs[qr][c4 * 4] =
            *(const float4*)(g_query + (size_t)(qb + qr) * DP + c4 * 4);
    }
    __syncthreads();

    float s = 0.f;
    #pragma unroll
    for (int u = 0; u < 16; u++) {
        int j = lane + u * 32;
        if (j < DDIM) {
            float v = qs[w][j];
            s = __fadd_rn(s, __fmul_rn(v, v));
        }
    }
    #pragma unroll
    for (int o = 16; o; o >>= 1)
        s = __fadd_rn(s, __shfl_down_sync(0xffffffffu, s, o));
    float qn = __shfl_sync(0xffffffffu, s, 0);

    float dzc = CUDART_INF_F;
    int   idxc = 0;
    if (lane < CAP) {
        idxc = g_cand[(size_t)q * CAP + lane];
        const float* drow = Dm + (size_t)idxc * DDIM;
        float dot = 0.f;
        for (int k = 0; k < DDIM; k++)
            dot = __fmaf_rn(qs[w][k], drow[k], dot);
        float xn = g_xn_emu[idxc];
        float t1 = __fadd_rn(qn, xn);
        dzc = __fsub_rn(t1, __fmul_rn(2.0f, dot));
    }

    float dz[CAP];
    int   ci[CAP];
    #pragma unroll
    for (int c = 0; c < CAP; c++) {
        dz[c] = __shfl_sync(0xffffffffu, dzc, c);
        ci[c] = __shfl_sync(0xffffffffu, idxc, c);
    }
    if (lane == 0) {
        #pragma unroll
        for (int r = 0; r < TOPK; r++) {
            int best = r;
            #pragma unroll
            for (int c = 0; c < CAP; c++) {
                if (c <= r) continue;
                if (dz[c] < dz[best] || (dz[c] == dz[best] && ci[c] < ci[best]))
                    best = c;
            }
            float td = dz[r]; dz[r] = dz[best]; dz[best] = td;
            int   tc = ci[r]; ci[r] = ci[best]; ci[best] = tc;
            out[(size_t)q * TOPK + r] = (float)ci[r];
        }
    }
}

extern "C" void kernel_launch(void* const* d_in, const int* in_sizes, int n_in,
                              void* d_out, int out_size) {
    const float* E  = nullptr;
    const float* P  = nullptr;
    const float* Dm = nullptr;
    for (int i = 0; i < n_in; i++) {
        long long sz = (long long)in_sizes[i];
        if (sz == (long long)NQ * NPIX)        E  = (const float*)d_in[i];
        else if (sz == (long long)NPIX * DDIM) P  = (const float*)d_in[i];
        else if (sz == (long long)ND * DDIM)   Dm = (const float*)d_in[i];
    }
    if (!E || !P || !Dm) {
        int idx[16];
        int m = n_in < 16 ? n_in : 16;
        for (int i = 0; i < m; i++) idx[i] = i;
        for (int a = 0; a < m; a++)
            for (int b = a + 1; b < m; b++)
                if ((long long)in_sizes[idx[b]] > (long long)in_sizes[idx[a]]) {
                    int tmp = idx[a]; idx[a] = idx[b]; idx[b] = tmp;
                }
        if (m >= 3) { Dm = (const float*)d_in[idx[0]];
                      E  = (const float*)d_in[idx[1]];
                      P  = (const float*)d_in[idx[2]]; }
    }
    if (!E || !P || !Dm) return;

    float* out = (float*)d_out;

    static bool attr_set = false;
    if (!attr_set) {
        cudaFuncSetAttribute(queryemu_kernel,
                             cudaFuncAttributeMaxDynamicSharedMemorySize,
                             KCH * 36 * (int)sizeof(float));
        cudaFuncSetAttribute(knn_mma,
                             cudaFuncAttributeMaxDynamicSharedMemorySize,
                             SMEM_KNN);
        attr_set = true;
    }

    rowmean_kernel<<<NQ, 256>>>(E);
    dictprep_kernel<<<ND / 4, 128>>>(Dm);
    queryemu_kernel<<<NQ / 32, 512, KCH * 36 * sizeof(float)>>>(E, P);
    knn_mma<<<NQ / 64, 256, SMEM_KNN>>>();
    refine_kernel<<<NQ / 4, 128>>>(Dm, out);
}